// round 16
// baseline (speedup 1.0000x reference)
#include <cuda_runtime.h>
#include <cuda_fp16.h>
#include <math.h>
#include <cstdint>

#define N_ROWS 8192
#define DIM    128
#define NCLS   1000
#define EPS    1e-8f
#define NTILE  64                          // 8192 / 128
#define NPAIRS (NTILE * (NTILE + 1) / 2)   // 2080

// ---------------- device scratch ----------------
__device__ __align__(16) __half g_xh[N_ROWS * DIM];          // fp16 normalized, 2 MB
__device__ float    g_p[N_ROWS];
__device__ float    g_num[N_ROWS];
__device__ float    g_den[N_ROWS];
__device__ unsigned g_maskbits[NCLS * (N_ROWS / 32)];        // [class][jword]

// ---------------- helpers ----------------
__device__ __forceinline__ float ex2f(float x) {
    float y; asm("ex2.approx.ftz.f32 %0, %1;" : "=f"(y) : "f"(x)); return y;
}
__device__ __forceinline__ uint32_t smem_u32(const void* p) {
    uint32_t a;
    asm("{ .reg .u64 t; cvta.to.shared.u64 t, %1; cvt.u32.u64 %0, t; }" : "=r"(a) : "l"(p));
    return a;
}
__device__ __forceinline__ void cp16(uint32_t dst, const void* src) {
    asm volatile("cp.async.cg.shared.global [%0], [%1], 16;" :: "r"(dst), "l"(src));
}
#define CP_COMMIT() asm volatile("cp.async.commit_group;" ::: "memory")
#define CP_WAIT(n)  asm volatile("cp.async.wait_group %0;" :: "n"(n) : "memory")

#define LDSM_X4(r0,r1,r2,r3,a) \
    asm volatile("ldmatrix.sync.aligned.m8n8.x4.shared.b16 {%0,%1,%2,%3}, [%4];" \
        : "=r"(r0),"=r"(r1),"=r"(r2),"=r"(r3) : "r"(a))

__device__ __forceinline__ void mma16816(float* d, const uint32_t* a, const uint32_t* b) {
    asm volatile("mma.sync.aligned.m16n8k16.row.col.f32.f16.f16.f32 "
        "{%0,%1,%2,%3}, {%4,%5,%6,%7}, {%8,%9}, {%0,%1,%2,%3};"
        : "+f"(d[0]), "+f"(d[1]), "+f"(d[2]), "+f"(d[3])
        : "r"(a[0]), "r"(a[1]), "r"(a[2]), "r"(a[3]), "r"(b[0]), "r"(b[1]));
}

// smem tile layout: 128 rows x 256B, 16B chunks XOR-swizzled by row
__device__ __forceinline__ uint32_t toff(int row, int ch) {
    return (uint32_t)(row * 256 + ((ch ^ (row & 7)) << 4));
}

#define OFF_B   32768
#define SMEM_TOTAL 65536   // A + B = 64 KB

// ---------------- kernel 1: fused prep (pipelined pack + normalize) ----------------
// grid: blocks 0..511 = pack (128 classes x 128 j-rows each, 4 pipelined subtiles)
//       blocks 512..767 = normalize (32 rows each)
__global__ void __launch_bounds__(256)
k_prep(const float* __restrict__ x,
       const float* __restrict__ proxy,
       const float* __restrict__ nm,
       const float* __restrict__ tp,
       const float* __restrict__ mp,
       float* __restrict__ out) {
    const int tid = threadIdx.x;

    if (blockIdx.x < 512) {
        // ---- pack role, pipelined over 4 subtiles of 32 j-rows ----
        __shared__ float s[2][32 * 132];        // double buffer, row stride 132
        const int pb = blockIdx.x;
        const int c0 = (pb & 7) * 128;
        const int jbase = (pb >> 3) * 128;      // 64 j-groups of 128 rows
        const int w = tid >> 5, lane = tid & 31;

        // prefetch subtiles 0 and 1 (each: 32 rows x 128 classes = 1024 float4)
        #pragma unroll
        for (int p = 0; p < 2; ++p) {
            const uint32_t sbase = smem_u32(s[p]);
            const int j0 = jbase + p * 32;
            #pragma unroll
            for (int it = 0; it < 4; ++it) {
                int idx = tid + it * 256;
                int j = idx >> 5, c = (idx & 31) * 4;
                if (c0 + c < NCLS)
                    cp16(sbase + (uint32_t)(j * 132 + c) * 4,
                         (const void*)(nm + (j0 + j) * NCLS + c0 + c));
            }
            CP_COMMIT();
        }

        #pragma unroll
        for (int st = 0; st < 4; ++st) {
            CP_WAIT(1);
            __syncthreads();
            const float* buf = s[st & 1];
            const int jw = (jbase >> 5) + st;
            #pragma unroll
            for (int q4 = 0; q4 < 4; ++q4) {
                int c = w * 16 + q4 * 4;
                float4 v = *(const float4*)&buf[lane * 132 + c];
                unsigned w0 = __ballot_sync(0xffffffffu, v.x > 0.5f);
                unsigned w1 = __ballot_sync(0xffffffffu, v.y > 0.5f);
                unsigned w2 = __ballot_sync(0xffffffffu, v.z > 0.5f);
                unsigned w3 = __ballot_sync(0xffffffffu, v.w > 0.5f);
                if (lane == 0 && c0 + c < NCLS) {
                    unsigned* dst = &g_maskbits[(c0 + c) * (N_ROWS / 32) + jw];
                    dst[0 * (N_ROWS / 32)] = w0;
                    dst[1 * (N_ROWS / 32)] = w1;
                    dst[2 * (N_ROWS / 32)] = w2;
                    dst[3 * (N_ROWS / 32)] = w3;
                }
            }
            __syncthreads();
            if (st + 2 < 4) {
                const uint32_t sbase = smem_u32(s[st & 1]);
                const int j0 = jbase + (st + 2) * 32;
                #pragma unroll
                for (int it = 0; it < 4; ++it) {
                    int idx = tid + it * 256;
                    int j = idx >> 5, c = (idx & 31) * 4;
                    if (c0 + c < NCLS)
                        cp16(sbase + (uint32_t)(j * 132 + c) * 4,
                             (const void*)(nm + (j0 + j) * NCLS + c0 + c));
                }
            }
            CP_COMMIT();   // commit every iteration to keep group accounting uniform
        }
    } else {
        // ---- normalize role: 32 rows per block, 4 per warp ----
        const int w = tid >> 5, lane = tid & 31;
        const int base = (blockIdx.x - 512) * 32;

        #pragma unroll
        for (int r = 0; r < 4; ++r) {
            int gw = base + w * 4 + r;
            const float4 v  = *(const float4*)(x + gw * DIM + lane * 4);
            const float4 pv = *(const float4*)(proxy + gw * DIM + lane * 4);
            float ssx = v.x * v.x + v.y * v.y + v.z * v.z + v.w * v.w;
            float ssp = pv.x * pv.x + pv.y * pv.y + pv.z * pv.z + pv.w * pv.w;
            float dot = v.x * pv.x + v.y * pv.y + v.z * pv.z + v.w * pv.w;

            #pragma unroll
            for (int o = 16; o; o >>= 1) {
                ssx += __shfl_xor_sync(0xffffffffu, ssx, o);
                ssp += __shfl_xor_sync(0xffffffffu, ssp, o);
                dot += __shfl_xor_sync(0xffffffffu, dot, o);
            }
            float invx = 1.0f / fmaxf(sqrtf(ssx), EPS);
            float invp = 1.0f / fmaxf(sqrtf(ssp), EPS);

            __half2 h0 = __floats2half2_rn(v.x * invx, v.y * invx);
            __half2 h1 = __floats2half2_rn(v.z * invx, v.w * invx);
            *(__half2*)(g_xh + gw * DIM + lane * 4)     = h0;
            *(__half2*)(g_xh + gw * DIM + lane * 4 + 2) = h1;

            if (lane == 0) {
                float T = tp[0], M = mp[0];
                float cosv = dot * invx * invp;
                g_p[gw]   = ex2f((cosv - M) * (1.4426950408889634f / T));
                g_num[gw] = 0.0f;
                g_den[gw] = 0.0f;
            }
        }
        if (blockIdx.x == 512 && tid == 0) out[0] = 0.0f;
    }
}

// ---------------- kernel 2: triangular fused GEMM, one tile-pair per CTA ----------------
__global__ void __launch_bounds__(256, 2)
k_main(const int* __restrict__ labels,
       const float* __restrict__ tp,
       const float* __restrict__ mp) {
    extern __shared__ char smem[];
    const uint32_t sb = smem_u32(smem);
    const int tid  = threadIdx.x;
    const int lane = tid & 31;
    const int wid  = tid >> 5;
    const int wm = wid >> 2;     // 0..1 : i block of 64
    const int wn = wid & 3;      // 0..3 : j block of 32

    // ---- triangular decode: blockIdx.x -> (bi, bj), bi <= bj ----
    const int z = blockIdx.x;
    int bi = (int)(64.5f - sqrtf(64.5f * 64.5f - 2.0f * (float)z));
    while (bi * (129 - bi) / 2 > z) --bi;
    while ((bi + 1) * (128 - bi) / 2 <= z) ++bi;
    const int bj = bi + (z - bi * (129 - bi) / 2);
    const int i0 = bi * 128, j0 = bj * 128;
    const bool offdiag = (bi != bj);

    const float T = tp[0], M = mp[0];
    const float scale = 1.4426950408889634f / T;
    const float nbias = -M * scale;

    // ---- prefetch: group 1 = k-chunks 0..7, group 2 = k-chunks 8..15 ----
    #pragma unroll
    for (int it = 0; it < 4; ++it) {
        int c = tid + it * 256;              // 0..1023: 128 rows x 8 chunks
        int row = c >> 3, ch = c & 7;
        cp16(sb + toff(row, ch),         (const void*)(g_xh + (i0 + row) * DIM + ch * 8));
        cp16(sb + OFF_B + toff(row, ch), (const void*)(g_xh + (j0 + row) * DIM + ch * 8));
    }
    CP_COMMIT();
    #pragma unroll
    for (int it = 0; it < 4; ++it) {
        int c = tid + it * 256;
        int row = c >> 3, ch = 8 + (c & 7);
        cp16(sb + toff(row, ch),         (const void*)(g_xh + (i0 + row) * DIM + ch * 8));
        cp16(sb + OFF_B + toff(row, ch), (const void*)(g_xh + (j0 + row) * DIM + ch * 8));
    }
    CP_COMMIT();

    // ldmatrix lane addressing
    const int arow_l = lane & 15;
    const int akc    = lane >> 4;
    const int bnt_h  = (lane >> 4) & 1;
    const int bkc    = (lane >> 3) & 1;
    const int brow_l = lane & 7;

    // row-side mask words + column labels, loaded in the cp.async shadow
    const int wword_row = (j0 >> 5) + wn;
    unsigned rw8[8];
    int lc8[8];
    #pragma unroll
    for (int r = 0; r < 8; ++r) {
        int ig = i0 + wm * 64 + (r >> 1) * 16 + (r & 1) * 8 + (lane >> 2);
        rw8[r] = g_maskbits[labels[ig] * (N_ROWS / 32) + wword_row];
    }
    #pragma unroll
    for (int nt = 0; nt < 4; ++nt)
        #pragma unroll
        for (int e = 0; e < 2; ++e)
            lc8[nt * 2 + e] = labels[j0 + wn * 32 + nt * 8 + (lane & 3) * 2 + e];

    float acc[4][4][4];
    #pragma unroll
    for (int a = 0; a < 4; ++a)
        #pragma unroll
        for (int b = 0; b < 4; ++b)
            #pragma unroll
            for (int q = 0; q < 4; ++q) acc[a][b][q] = 0.0f;

    // ---- first k-half: chunks 0..7 (kk 0..3) ----
    CP_WAIT(1);
    __syncthreads();
    #pragma unroll
    for (int kk = 0; kk < 4; ++kk) {
        uint32_t ah[4][4], bh[4][2];
        #pragma unroll
        for (int mt = 0; mt < 4; ++mt) {
            int row = wm * 64 + mt * 16 + arow_l;
            LDSM_X4(ah[mt][0], ah[mt][1], ah[mt][2], ah[mt][3], sb + toff(row, kk * 2 + akc));
        }
        #pragma unroll
        for (int ntp = 0; ntp < 2; ++ntp) {
            int row = wn * 32 + (ntp * 2 + bnt_h) * 8 + brow_l;
            LDSM_X4(bh[ntp * 2][0], bh[ntp * 2][1],
                    bh[ntp * 2 + 1][0], bh[ntp * 2 + 1][1],
                    sb + OFF_B + toff(row, kk * 2 + bkc));
        }
        #pragma unroll
        for (int mt = 0; mt < 4; ++mt)
            #pragma unroll
            for (int nt = 0; nt < 4; ++nt)
                mma16816(acc[mt][nt], ah[mt], bh[nt]);
    }

    // ---- second k-half: chunks 8..15 (kk 4..7) ----
    CP_WAIT(0);
    __syncthreads();
    #pragma unroll
    for (int kk = 4; kk < 8; ++kk) {
        uint32_t ah[4][4], bh[4][2];
        #pragma unroll
        for (int mt = 0; mt < 4; ++mt) {
            int row = wm * 64 + mt * 16 + arow_l;
            LDSM_X4(ah[mt][0], ah[mt][1], ah[mt][2], ah[mt][3], sb + toff(row, kk * 2 + akc));
        }
        #pragma unroll
        for (int ntp = 0; ntp < 2; ++ntp) {
            int row = wn * 32 + (ntp * 2 + bnt_h) * 8 + brow_l;
            LDSM_X4(bh[ntp * 2][0], bh[ntp * 2][1],
                    bh[ntp * 2 + 1][0], bh[ntp * 2 + 1][1],
                    sb + OFF_B + toff(row, kk * 2 + bkc));
        }
        #pragma unroll
        for (int mt = 0; mt < 4; ++mt)
            #pragma unroll
            for (int nt = 0; nt < 4; ++nt)
                mma16816(acc[mt][nt], ah[mt], bh[nt]);
    }

    // ---- exp in place (diag check only on diagonal CTAs) ----
    if (offdiag) {
        #pragma unroll
        for (int mt = 0; mt < 4; ++mt)
            #pragma unroll
            for (int nt = 0; nt < 4; ++nt)
                #pragma unroll
                for (int q = 0; q < 4; ++q)
                    acc[mt][nt][q] = ex2f(fmaf(acc[mt][nt][q], scale, nbias));
    } else {
        #pragma unroll
        for (int mt = 0; mt < 4; ++mt)
            #pragma unroll
            for (int h = 0; h < 2; ++h) {
                const int il = wm * 64 + mt * 16 + h * 8 + (lane >> 2);
                #pragma unroll
                for (int nt = 0; nt < 4; ++nt)
                    #pragma unroll
                    for (int e = 0; e < 2; ++e) {
                        const int jl = wn * 32 + nt * 8 + (lane & 3) * 2 + e;
                        float ex = ex2f(fmaf(acc[mt][nt][h * 2 + e], scale, nbias));
                        acc[mt][nt][h * 2 + e] = (il == jl) ? 0.0f : ex;
                    }
            }
    }

    // ---- row side: den_i / num_i ----
    #pragma unroll
    for (int mt = 0; mt < 4; ++mt) {
        #pragma unroll
        for (int h = 0; h < 2; ++h) {
            const int r = mt * 2 + h;
            const unsigned w = rw8[r];
            float de = 0.0f, nu = 0.0f;
            #pragma unroll
            for (int nt = 0; nt < 4; ++nt)
                #pragma unroll
                for (int e = 0; e < 2; ++e) {
                    int col = wn * 32 + nt * 8 + (lane & 3) * 2 + e;
                    float ex = acc[mt][nt][h * 2 + e];
                    de += ex;
                    nu += ((w >> (col & 31)) & 1u) ? ex : 0.0f;
                }
            #pragma unroll
            for (int m = 1; m <= 2; m <<= 1) {
                de += __shfl_xor_sync(0xffffffffu, de, m);
                nu += __shfl_xor_sync(0xffffffffu, nu, m);
            }
            if ((lane & 3) == 0) {
                int ig = i0 + wm * 64 + mt * 16 + h * 8 + (lane >> 2);
                atomicAdd(&g_den[ig], de);
                atomicAdd(&g_num[ig], nu);
            }
        }
    }

    // ---- column side (off-diagonal only) ----
    if (offdiag) {
        #pragma unroll
        for (int nt = 0; nt < 4; ++nt) {
            #pragma unroll
            for (int e = 0; e < 2; ++e) {
                const int lc = lc8[nt * 2 + e];
                const unsigned cw0 = g_maskbits[lc * (N_ROWS / 32) + (i0 >> 5) + wm * 2];
                const unsigned cw1 = g_maskbits[lc * (N_ROWS / 32) + (i0 >> 5) + wm * 2 + 1];
                float cd = 0.0f, cn = 0.0f;
                #pragma unroll
                for (int mt = 0; mt < 4; ++mt)
                    #pragma unroll
                    for (int h = 0; h < 2; ++h) {
                        float ex = acc[mt][nt][h * 2 + e];
                        const unsigned w = (mt >= 2) ? cw1 : cw0;
                        const int bit = (mt * 16 + h * 8 + (lane >> 2)) & 31;
                        cd += ex;
                        cn += ((w >> bit) & 1u) ? ex : 0.0f;
                    }
                #pragma unroll
                for (int m = 4; m <= 16; m <<= 1) {
                    cd += __shfl_xor_sync(0xffffffffu, cd, m);
                    cn += __shfl_xor_sync(0xffffffffu, cn, m);
                }
                if ((lane >> 2) == 0) {
                    int jg = j0 + wn * 32 + nt * 8 + (lane & 3) * 2 + e;
                    atomicAdd(&g_den[jg], cd);
                    atomicAdd(&g_num[jg], cn);
                }
            }
        }
    }
}

// ---------------- kernel 3: final loss reduction (32 blocks, atomic) ----------------
__global__ void __launch_bounds__(256)
k_final(float* __restrict__ out, const float* __restrict__ tp) {
    __shared__ float s[256];
    float T = tp[0];
    int r = blockIdx.x * 256 + threadIdx.x;
    float p = g_p[r];
    float sum = -__logf(T * (p + g_num[r]) / (p + g_den[r]));
    s[threadIdx.x] = sum;
    __syncthreads();
    #pragma unroll
    for (int o = 128; o >= 32; o >>= 1) {
        if (threadIdx.x < o) s[threadIdx.x] += s[threadIdx.x + o];
        __syncthreads();
    }
    if (threadIdx.x < 32) {
        float v = s[threadIdx.x];
        #pragma unroll
        for (int m = 16; m; m >>= 1) v += __shfl_xor_sync(0xffffffffu, v, m);
        if (threadIdx.x == 0) atomicAdd(out, v / (float)N_ROWS);
    }
}

// ---------------- launch ----------------
extern "C" void kernel_launch(void* const* d_in, const int* in_sizes, int n_in,
                              void* d_out, int out_size) {
    const float* inst  = (const float*)d_in[0];
    const float* proxy = (const float*)d_in[1];
    const float* nmask = (const float*)d_in[2];
    const int*   lab   = (const int*)d_in[3];
    const float* temp  = (const float*)d_in[4];
    const float* marg  = (const float*)d_in[5];
    float* out = (float*)d_out;

    cudaFuncSetAttribute(k_main, cudaFuncAttributeMaxDynamicSharedMemorySize, SMEM_TOTAL);

    k_prep<<<512 + 256, 256>>>(inst, proxy, nmask, temp, marg, out);
    k_main<<<NPAIRS, 256, SMEM_TOTAL>>>(lab, temp, marg);
    k_final<<<32, 256>>>(out, temp);
}

// round 17
// speedup vs baseline: 1.2071x; 1.2071x over previous
#include <cuda_runtime.h>
#include <cuda_fp16.h>
#include <math.h>
#include <cstdint>

#define N_ROWS 8192
#define DIM    128
#define NCLS   1000
#define EPS    1e-8f
#define NTILE  64                          // 8192 / 128
#define NPAIRS (NTILE * (NTILE + 1) / 2)   // 2080

// ---------------- device scratch ----------------
__device__ __align__(16) __half g_xh[N_ROWS * DIM];          // fp16 normalized, 2 MB
__device__ float    g_p[N_ROWS];
__device__ float    g_num[N_ROWS];
__device__ float    g_den[N_ROWS];
__device__ unsigned g_maskbits[NCLS * (N_ROWS / 32)];        // [class][jword]

// ---------------- helpers ----------------
__device__ __forceinline__ float ex2f(float x) {
    float y; asm("ex2.approx.ftz.f32 %0, %1;" : "=f"(y) : "f"(x)); return y;
}
__device__ __forceinline__ uint32_t smem_u32(const void* p) {
    uint32_t a;
    asm("{ .reg .u64 t; cvta.to.shared.u64 t, %1; cvt.u32.u64 %0, t; }" : "=r"(a) : "l"(p));
    return a;
}
__device__ __forceinline__ void cp16(uint32_t dst, const void* src) {
    asm volatile("cp.async.cg.shared.global [%0], [%1], 16;" :: "r"(dst), "l"(src));
}
#define CP_COMMIT() asm volatile("cp.async.commit_group;" ::: "memory")
#define CP_WAIT(n)  asm volatile("cp.async.wait_group %0;" :: "n"(n) : "memory")

#define LDSM_X4(r0,r1,r2,r3,a) \
    asm volatile("ldmatrix.sync.aligned.m8n8.x4.shared.b16 {%0,%1,%2,%3}, [%4];" \
        : "=r"(r0),"=r"(r1),"=r"(r2),"=r"(r3) : "r"(a))

__device__ __forceinline__ void mma16816(float* d, const uint32_t* a, const uint32_t* b) {
    asm volatile("mma.sync.aligned.m16n8k16.row.col.f32.f16.f16.f32 "
        "{%0,%1,%2,%3}, {%4,%5,%6,%7}, {%8,%9}, {%0,%1,%2,%3};"
        : "+f"(d[0]), "+f"(d[1]), "+f"(d[2]), "+f"(d[3])
        : "r"(a[0]), "r"(a[1]), "r"(a[2]), "r"(a[3]), "r"(b[0]), "r"(b[1]));
}

// smem tile layout: 128 rows x 256B, 16B chunks XOR-swizzled by row
__device__ __forceinline__ uint32_t toff(int row, int ch) {
    return (uint32_t)(row * 256 + ((ch ^ (row & 7)) << 4));
}

#define OFF_B   32768
#define SMEM_TOTAL 65536   // A + B = 64 KB

// ---------------- kernel 1: fused prep (normalize + pack + out zero) ----------------
__global__ void __launch_bounds__(256)
k_prep(const float* __restrict__ x,
       const float* __restrict__ proxy,
       const float* __restrict__ nm,
       const float* __restrict__ tp,
       const float* __restrict__ mp,
       float* __restrict__ out) {
    const int tid = threadIdx.x;

    if (blockIdx.x < 1024) {
        // ---- normalize role: 8 warps = 8 rows per block ----
        int gw   = blockIdx.x * 8 + (tid >> 5);
        int lane = tid & 31;

        const float4 v  = *(const float4*)(x + gw * DIM + lane * 4);
        float ssx = v.x * v.x + v.y * v.y + v.z * v.z + v.w * v.w;
        const float4 pv = *(const float4*)(proxy + gw * DIM + lane * 4);
        float ssp = pv.x * pv.x + pv.y * pv.y + pv.z * pv.z + pv.w * pv.w;
        float dot = v.x * pv.x + v.y * pv.y + v.z * pv.z + v.w * pv.w;

        #pragma unroll
        for (int o = 16; o; o >>= 1) {
            ssx += __shfl_xor_sync(0xffffffffu, ssx, o);
            ssp += __shfl_xor_sync(0xffffffffu, ssp, o);
            dot += __shfl_xor_sync(0xffffffffu, dot, o);
        }
        float invx = 1.0f / fmaxf(sqrtf(ssx), EPS);
        float invp = 1.0f / fmaxf(sqrtf(ssp), EPS);

        __half2 h0 = __floats2half2_rn(v.x * invx, v.y * invx);
        __half2 h1 = __floats2half2_rn(v.z * invx, v.w * invx);
        *(__half2*)(g_xh + gw * DIM + lane * 4)     = h0;
        *(__half2*)(g_xh + gw * DIM + lane * 4 + 2) = h1;

        if (lane == 0) {
            float T = tp[0], M = mp[0];
            float cosv = dot * invx * invp;
            g_p[gw]   = ex2f((cosv - M) * (1.4426950408889634f / T));
            g_num[gw] = 0.0f;
            g_den[gw] = 0.0f;
        }
        if (blockIdx.x == 0 && tid == 0) out[0] = 0.0f;
    } else {
        // ---- pack role: 32 j-rows x 128 classes per block, cp.async + float4 LDS ----
        __shared__ float s[32 * 132];            // row stride 132 floats (16B-aligned)
        const int pb = blockIdx.x - 1024;        // 0..2047
        const int c0 = (pb & 7) * 128;
        const int j0 = (pb >> 3) * 32;
        const uint32_t sbase = smem_u32(s);
        #pragma unroll
        for (int it = 0; it < 4; ++it) {
            int idx = tid + it * 256;            // 0..1023 float4 slots
            int j = idx >> 5, c = (idx & 31) * 4;
            if (c0 + c < NCLS)                   // NCLS % 4 == 0: no straddle
                cp16(sbase + (uint32_t)(j * 132 + c) * 4,
                     (const void*)(nm + (j0 + j) * NCLS + c0 + c));
        }
        CP_COMMIT();
        CP_WAIT(0);
        __syncthreads();
        const int w = tid >> 5, lane = tid & 31;
        #pragma unroll
        for (int q4 = 0; q4 < 4; ++q4) {
            int c = w * 16 + q4 * 4;
            float4 v = *(const float4*)&s[lane * 132 + c];
            unsigned w0 = __ballot_sync(0xffffffffu, v.x > 0.5f);
            unsigned w1 = __ballot_sync(0xffffffffu, v.y > 0.5f);
            unsigned w2 = __ballot_sync(0xffffffffu, v.z > 0.5f);
            unsigned w3 = __ballot_sync(0xffffffffu, v.w > 0.5f);
            if (lane == 0 && c0 + c < NCLS) {
                unsigned* dst = &g_maskbits[(c0 + c) * (N_ROWS / 32) + (j0 >> 5)];
                dst[0 * (N_ROWS / 32)] = w0;
                dst[1 * (N_ROWS / 32)] = w1;
                dst[2 * (N_ROWS / 32)] = w2;
                dst[3 * (N_ROWS / 32)] = w3;
            }
        }
    }
}

// ---------------- kernel 2: triangular fused GEMM, one tile-pair per CTA ----------------
__global__ void __launch_bounds__(256, 2)
k_main(const int* __restrict__ labels,
       const float* __restrict__ tp,
       const float* __restrict__ mp) {
    extern __shared__ char smem[];
    const uint32_t sb = smem_u32(smem);
    const int tid  = threadIdx.x;
    const int lane = tid & 31;
    const int wid  = tid >> 5;
    const int wm = wid >> 2;     // 0..1 : i block of 64
    const int wn = wid & 3;      // 0..3 : j block of 32

    // ---- triangular decode: blockIdx.x -> (bi, bj), bi <= bj ----
    const int z = blockIdx.x;
    int bi = (int)(64.5f - sqrtf(64.5f * 64.5f - 2.0f * (float)z));
    while (bi * (129 - bi) / 2 > z) --bi;
    while ((bi + 1) * (128 - bi) / 2 <= z) ++bi;
    const int bj = bi + (z - bi * (129 - bi) / 2);
    const int i0 = bi * 128, j0 = bj * 128;
    const bool offdiag = (bi != bj);

    const float T = tp[0], M = mp[0];
    const float scale = 1.4426950408889634f / T;
    const float nbias = -M * scale;

    // ---- prefetch: group 1 = k-chunks 0..7, group 2 = k-chunks 8..15 ----
    #pragma unroll
    for (int it = 0; it < 4; ++it) {
        int c = tid + it * 256;              // 0..1023: 128 rows x 8 chunks
        int row = c >> 3, ch = c & 7;
        cp16(sb + toff(row, ch),         (const void*)(g_xh + (i0 + row) * DIM + ch * 8));
        cp16(sb + OFF_B + toff(row, ch), (const void*)(g_xh + (j0 + row) * DIM + ch * 8));
    }
    CP_COMMIT();
    #pragma unroll
    for (int it = 0; it < 4; ++it) {
        int c = tid + it * 256;
        int row = c >> 3, ch = 8 + (c & 7);
        cp16(sb + toff(row, ch),         (const void*)(g_xh + (i0 + row) * DIM + ch * 8));
        cp16(sb + OFF_B + toff(row, ch), (const void*)(g_xh + (j0 + row) * DIM + ch * 8));
    }
    CP_COMMIT();

    // ldmatrix lane addressing
    const int arow_l = lane & 15;
    const int akc    = lane >> 4;
    const int bnt_h  = (lane >> 4) & 1;
    const int bkc    = (lane >> 3) & 1;
    const int brow_l = lane & 7;

    // row-side mask words + column labels, loaded in the cp.async shadow
    const int wword_row = (j0 >> 5) + wn;
    unsigned rw8[8];
    int lc8[8];
    #pragma unroll
    for (int r = 0; r < 8; ++r) {
        int ig = i0 + wm * 64 + (r >> 1) * 16 + (r & 1) * 8 + (lane >> 2);
        rw8[r] = g_maskbits[labels[ig] * (N_ROWS / 32) + wword_row];
    }
    #pragma unroll
    for (int nt = 0; nt < 4; ++nt)
        #pragma unroll
        for (int e = 0; e < 2; ++e)
            lc8[nt * 2 + e] = labels[j0 + wn * 32 + nt * 8 + (lane & 3) * 2 + e];

    float acc[4][4][4];
    #pragma unroll
    for (int a = 0; a < 4; ++a)
        #pragma unroll
        for (int b = 0; b < 4; ++b)
            #pragma unroll
            for (int q = 0; q < 4; ++q) acc[a][b][q] = 0.0f;

    // ---- first k-half: chunks 0..7 (kk 0..3) ----
    CP_WAIT(1);
    __syncthreads();
    #pragma unroll
    for (int kk = 0; kk < 4; ++kk) {
        uint32_t ah[4][4], bh[4][2];
        #pragma unroll
        for (int mt = 0; mt < 4; ++mt) {
            int row = wm * 64 + mt * 16 + arow_l;
            LDSM_X4(ah[mt][0], ah[mt][1], ah[mt][2], ah[mt][3], sb + toff(row, kk * 2 + akc));
        }
        #pragma unroll
        for (int ntp = 0; ntp < 2; ++ntp) {
            int row = wn * 32 + (ntp * 2 + bnt_h) * 8 + brow_l;
            LDSM_X4(bh[ntp * 2][0], bh[ntp * 2][1],
                    bh[ntp * 2 + 1][0], bh[ntp * 2 + 1][1],
                    sb + OFF_B + toff(row, kk * 2 + bkc));
        }
        #pragma unroll
        for (int mt = 0; mt < 4; ++mt)
            #pragma unroll
            for (int nt = 0; nt < 4; ++nt)
                mma16816(acc[mt][nt], ah[mt], bh[nt]);
    }

    // ---- second k-half: chunks 8..15 (kk 4..7) ----
    CP_WAIT(0);
    __syncthreads();
    #pragma unroll
    for (int kk = 4; kk < 8; ++kk) {
        uint32_t ah[4][4], bh[4][2];
        #pragma unroll
        for (int mt = 0; mt < 4; ++mt) {
            int row = wm * 64 + mt * 16 + arow_l;
            LDSM_X4(ah[mt][0], ah[mt][1], ah[mt][2], ah[mt][3], sb + toff(row, kk * 2 + akc));
        }
        #pragma unroll
        for (int ntp = 0; ntp < 2; ++ntp) {
            int row = wn * 32 + (ntp * 2 + bnt_h) * 8 + brow_l;
            LDSM_X4(bh[ntp * 2][0], bh[ntp * 2][1],
                    bh[ntp * 2 + 1][0], bh[ntp * 2 + 1][1],
                    sb + OFF_B + toff(row, kk * 2 + bkc));
        }
        #pragma unroll
        for (int mt = 0; mt < 4; ++mt)
            #pragma unroll
            for (int nt = 0; nt < 4; ++nt)
                mma16816(acc[mt][nt], ah[mt], bh[nt]);
    }

    // ---- column-side mask words: issue early so row-side work hides their latency ----
    unsigned cw[8][2];
    if (offdiag) {
        #pragma unroll
        for (int r = 0; r < 8; ++r) {
            const unsigned* mrow = &g_maskbits[lc8[r] * (N_ROWS / 32) + (i0 >> 5) + wm * 2];
            cw[r][0] = mrow[0];
            cw[r][1] = mrow[1];
        }
    }

    // ---- exp in place (diag check only on diagonal CTAs) ----
    if (offdiag) {
        #pragma unroll
        for (int mt = 0; mt < 4; ++mt)
            #pragma unroll
            for (int nt = 0; nt < 4; ++nt)
                #pragma unroll
                for (int q = 0; q < 4; ++q)
                    acc[mt][nt][q] = ex2f(fmaf(acc[mt][nt][q], scale, nbias));
    } else {
        #pragma unroll
        for (int mt = 0; mt < 4; ++mt)
            #pragma unroll
            for (int h = 0; h < 2; ++h) {
                const int il = wm * 64 + mt * 16 + h * 8 + (lane >> 2);
                #pragma unroll
                for (int nt = 0; nt < 4; ++nt)
                    #pragma unroll
                    for (int e = 0; e < 2; ++e) {
                        const int jl = wn * 32 + nt * 8 + (lane & 3) * 2 + e;
                        float ex = ex2f(fmaf(acc[mt][nt][h * 2 + e], scale, nbias));
                        acc[mt][nt][h * 2 + e] = (il == jl) ? 0.0f : ex;
                    }
            }
    }

    // ---- row side: den_i / num_i ----
    #pragma unroll
    for (int mt = 0; mt < 4; ++mt) {
        #pragma unroll
        for (int h = 0; h < 2; ++h) {
            const int r = mt * 2 + h;
            const unsigned w = rw8[r];
            float de = 0.0f, nu = 0.0f;
            #pragma unroll
            for (int nt = 0; nt < 4; ++nt)
                #pragma unroll
                for (int e = 0; e < 2; ++e) {
                    int col = wn * 32 + nt * 8 + (lane & 3) * 2 + e;
                    float ex = acc[mt][nt][h * 2 + e];
                    de += ex;
                    nu += ((w >> (col & 31)) & 1u) ? ex : 0.0f;
                }
            #pragma unroll
            for (int m = 1; m <= 2; m <<= 1) {
                de += __shfl_xor_sync(0xffffffffu, de, m);
                nu += __shfl_xor_sync(0xffffffffu, nu, m);
            }
            if ((lane & 3) == 0) {
                int ig = i0 + wm * 64 + mt * 16 + h * 8 + (lane >> 2);
                atomicAdd(&g_den[ig], de);
                atomicAdd(&g_num[ig], nu);
            }
        }
    }

    // ---- column side (off-diagonal only) ----
    if (offdiag) {
        #pragma unroll
        for (int nt = 0; nt < 4; ++nt) {
            #pragma unroll
            for (int e = 0; e < 2; ++e) {
                const int r = nt * 2 + e;
                float cd = 0.0f, cn = 0.0f;
                #pragma unroll
                for (int mt = 0; mt < 4; ++mt)
                    #pragma unroll
                    for (int h = 0; h < 2; ++h) {
                        float ex = acc[mt][nt][h * 2 + e];
                        const unsigned w = cw[r][mt >> 1];
                        const int bit = (mt * 16 + h * 8 + (lane >> 2)) & 31;
                        cd += ex;
                        cn += ((w >> bit) & 1u) ? ex : 0.0f;
                    }
                #pragma unroll
                for (int m = 4; m <= 16; m <<= 1) {
                    cd += __shfl_xor_sync(0xffffffffu, cd, m);
                    cn += __shfl_xor_sync(0xffffffffu, cn, m);
                }
                if ((lane >> 2) == 0) {
                    int jg = j0 + wn * 32 + nt * 8 + (lane & 3) * 2 + e;
                    atomicAdd(&g_den[jg], cd);
                    atomicAdd(&g_num[jg], cn);
                }
            }
        }
    }
}

// ---------------- kernel 3: final loss reduction (32 blocks, atomic) ----------------
__global__ void __launch_bounds__(256)
k_final(float* __restrict__ out, const float* __restrict__ tp) {
    __shared__ float s[256];
    float T = tp[0];
    int r = blockIdx.x * 256 + threadIdx.x;
    float p = g_p[r];
    float sum = -__logf(T * (p + g_num[r]) / (p + g_den[r]));
    s[threadIdx.x] = sum;
    __syncthreads();
    #pragma unroll
    for (int o = 128; o >= 32; o >>= 1) {
        if (threadIdx.x < o) s[threadIdx.x] += s[threadIdx.x + o];
        __syncthreads();
    }
    if (threadIdx.x < 32) {
        float v = s[threadIdx.x];
        #pragma unroll
        for (int m = 16; m; m >>= 1) v += __shfl_xor_sync(0xffffffffu, v, m);
        if (threadIdx.x == 0) atomicAdd(out, v / (float)N_ROWS);
    }
}

// ---------------- launch ----------------
extern "C" void kernel_launch(void* const* d_in, const int* in_sizes, int n_in,
                              void* d_out, int out_size) {
    const float* inst  = (const float*)d_in[0];
    const float* proxy = (const float*)d_in[1];
    const float* nmask = (const float*)d_in[2];
    const int*   lab   = (const int*)d_in[3];
    const float* temp  = (const float*)d_in[4];
    const float* marg  = (const float*)d_in[5];
    float* out = (float*)d_out;

    cudaFuncSetAttribute(k_main, cudaFuncAttributeMaxDynamicSharedMemorySize, SMEM_TOTAL);

    k_prep<<<1024 + 2048, 256>>>(inst, proxy, nmask, temp, marg, out);
    k_main<<<NPAIRS, 256, SMEM_TOTAL>>>(lab, temp, marg);
    k_final<<<32, 256>>>(out, temp);
}